// round 12
// baseline (speedup 1.0000x reference)
#include <cuda_runtime.h>
#include <cuda_fp16.h>
#include <math.h>

#define Nn 100000
#define Emax 1600000
#define ETmax (Emax + Nn)
#define NB 98                 // (Nn + 1023) / 1024
#define BN_EPS 1e-5f
#define LRELU 0.2f

// ---- scratch (static device globals; no allocation) ----
__device__ float g_H[Nn * 64];        // transformed features (fp32 rows L1/L2; fp16 rows L3)
__device__ float g_X[Nn * 64];        // post-layer features
__device__ float g_alS[Nn * 4];
__device__ float g_alD[Nn * 4];
__device__ int   g_deg[Nn];
__device__ int   g_rowoff[Nn + 1];
__device__ int   g_cursor[Nn];
__device__ int   g_adj[ETmax];
__device__ int   g_bsum[NB];
__device__ int   g_boff[NB];
__device__ float g_pooled2[64 * 32];  // [channel][slot] partial pooled sums
__device__ unsigned g_mEnc[12];       // order-encoded per-layer per-head global alS max

// order-preserving float<->uint encoding (for atomicMax on floats incl. negatives)
__device__ __forceinline__ unsigned encF(float f) {
    unsigned u = __float_as_uint(f);
    return (u & 0x80000000u) ? ~u : (u | 0x80000000u);
}
__device__ __forceinline__ float decF(unsigned e) {
    unsigned u = (e & 0x80000000u) ? (e & 0x7FFFFFFFu) : ~e;
    return __uint_as_float(u);
}
__device__ __forceinline__ float lrelu(float x) { return x > 0.f ? x : LRELU * x; }

// ---------------- CSR build ----------------
__global__ void __launch_bounds__(256) k_init() {
    int i = blockIdx.x * blockDim.x + threadIdx.x;
    if (i < Nn) g_deg[i] = 1;          // self-loop
    if (i < 64 * 32) g_pooled2[i] = 0.f;
    if (i < 12) g_mEnc[i] = 0u;        // below any real encoded float
}

__global__ void __launch_bounds__(256) k_count(const int* __restrict__ dst, int E) {
    int i = blockIdx.x * blockDim.x + threadIdx.x;
    if (i < E) atomicAdd(&g_deg[dst[i]], 1);
}

// phase 1: per-1024-block sums
__global__ void __launch_bounds__(1024) k_scan1() {
    int i = blockIdx.x * 1024 + threadIdx.x;
    int lane = threadIdx.x & 31, wid = threadIdx.x >> 5;
    int d = (i < Nn) ? g_deg[i] : 0;
#pragma unroll
    for (int off = 16; off; off >>= 1) d += __shfl_xor_sync(0xffffffffu, d, off);
    __shared__ int ws[32];
    if (lane == 0) ws[wid] = d;
    __syncthreads();
    if (threadIdx.x < 32) {
        int t = ws[threadIdx.x];
#pragma unroll
        for (int off = 16; off; off >>= 1) t += __shfl_xor_sync(0xffffffffu, t, off);
        if (threadIdx.x == 0) g_bsum[blockIdx.x] = t;
    }
}

// phase 2: scan 98 block sums (1 block, 128 threads)
__global__ void __launch_bounds__(128) k_scan2(int total) {
    int t = threadIdx.x;
    int lane = t & 31, wid = t >> 5;
    int v = (t < NB) ? g_bsum[t] : 0;
    int x = v;
#pragma unroll
    for (int off = 1; off < 32; off <<= 1) {
        int y = __shfl_up_sync(0xffffffffu, x, off);
        if (lane >= off) x += y;
    }
    __shared__ int ws[4];
    if (lane == 31) ws[wid] = x;
    __syncthreads();
    int add = 0;
#pragma unroll
    for (int w = 0; w < 4; w++) if (w < wid) add += ws[w];
    if (t < NB) g_boff[t] = x + add - v;   // exclusive
    if (t == 0) g_rowoff[Nn] = total;
}

// phase 3: per-block exclusive scan + scatter rowoff/cursor
__global__ void __launch_bounds__(1024) k_scan3() {
    int i = blockIdx.x * 1024 + threadIdx.x;
    int lane = threadIdx.x & 31, wid = threadIdx.x >> 5;
    int d = (i < Nn) ? g_deg[i] : 0;
    int x = d;
#pragma unroll
    for (int off = 1; off < 32; off <<= 1) {
        int y = __shfl_up_sync(0xffffffffu, x, off);
        if (lane >= off) x += y;
    }
    __shared__ int ws[32];
    if (lane == 31) ws[wid] = x;
    __syncthreads();
    if (wid == 0) {
        int y = ws[lane];
        int z = y;
#pragma unroll
        for (int off = 1; off < 32; off <<= 1) {
            int q = __shfl_up_sync(0xffffffffu, z, off);
            if (lane >= off) z += q;
        }
        ws[lane] = z - y;   // exclusive warp offsets
    }
    __syncthreads();
    int excl = x - d + ws[wid] + g_boff[blockIdx.x];
    if (i < Nn) { g_rowoff[i] = excl; g_cursor[i] = excl; }
}

__global__ void __launch_bounds__(256) k_fill(const int* __restrict__ src,
                                              const int* __restrict__ dst, int E) {
    int i = blockIdx.x * blockDim.x + threadIdx.x;
    int tot = E + Nn;
    if (i >= tot) return;
    int s, d;
    if (i < E) { s = src[i]; d = dst[i]; }
    else       { s = i - E; d = s; }
    int p = atomicAdd(&g_cursor[d], 1);
    g_adj[p] = s;
}

// ---------------- linear + attention-logit kernel (f32x2 packed FMA) ----------------
// HSTORE (layer 3): g_H row stored as 64 fp16 (128 B) — consumed only by the
// mean-pooled layer-3 aggregation, where independent quantization noise cancels.
template <int IN, int HEADS, bool HSTORE>
__global__ void __launch_bounds__(128) k_lin(const float* __restrict__ xin,
                                             const float* __restrict__ W,
                                             const float* __restrict__ asrc,
                                             const float* __restrict__ adst,
                                             int layer) {
    constexpr int TB = 128;
    constexpr int XS = (IN == 64) ? 65 : IN;
    __shared__ __align__(16) float Wsh[64 * IN];
    __shared__ __align__(16) float xsh[TB * ((IN == 64) ? 65 : IN)];
    int tid = threadIdx.x;
    int lane = tid & 31;
    int vbase = blockIdx.x * TB;

    for (int i = tid; i < 64 * IN; i += TB) {
        int c = i / IN, k = i % IN;
        Wsh[k * 64 + c] = W[i];          // transposed: Wsh[k][c]
    }
    const float* srcp = (IN == 64) ? (const float*)g_X : xin;
    for (int i = tid; i < TB * IN; i += TB) {
        int node = i / IN, k = i % IN;
        int v = vbase + node;
        xsh[node * XS + k] = (v < Nn) ? srcp[(size_t)v * IN + k] : 0.f;
    }
    __syncthreads();

    unsigned long long acc2[32];
#pragma unroll
    for (int j = 0; j < 32; j++) acc2[j] = 0ull;   // bits 0 == {+0.f,+0.f}

#pragma unroll 4
    for (int k = 0; k < IN; k++) {
        float xk = xsh[tid * XS + k];
        unsigned long long xk2;
        asm("mov.b64 %0, {%1, %1};" : "=l"(xk2) : "f"(xk));
        const unsigned long long* Wp = (const unsigned long long*)(Wsh + k * 64);
#pragma unroll
        for (int j = 0; j < 32; j++) {
            asm("fma.rn.f32x2 %0, %1, %2, %0;" : "+l"(acc2[j]) : "l"(Wp[j]), "l"(xk2));
        }
    }

    float accf[64];
#pragma unroll
    for (int j = 0; j < 32; j++) {
        asm("mov.b64 {%0, %1}, %2;" : "=f"(accf[2 * j]), "=f"(accf[2 * j + 1]) : "l"(acc2[j]));
    }

    int v = vbase + tid;
    bool valid = (v < Nn);
    constexpr int C = 64 / HEADS;
    float mx[HEADS];
#pragma unroll
    for (int h = 0; h < HEADS; h++) {
        float s1 = 0.f, s2 = 0.f;
#pragma unroll
        for (int j = 0; j < C; j++) {
            float t = accf[h * C + j];
            s1 += t * asrc[h * C + j];
            s2 += t * adst[h * C + j];
        }
        if (valid) {
            g_alS[(size_t)v * HEADS + h] = s1;
            g_alD[(size_t)v * HEADS + h] = s2;
        }
        mx[h] = valid ? s1 : -3.4e38f;
    }
    // warp-reduce max per head, one atomic per warp per head
#pragma unroll
    for (int h = 0; h < HEADS; h++) {
#pragma unroll
        for (int off = 16; off; off >>= 1)
            mx[h] = fmaxf(mx[h], __shfl_xor_sync(0xffffffffu, mx[h], off));
        if (lane == 0) atomicMax(&g_mEnc[layer * 4 + h], encF(mx[h]));
    }

    __syncthreads();
    if (HSTORE) {
        // pack to fp16 pairs, stage through smem, coalesced 32-uint row copy
        unsigned* xshu = (unsigned*)xsh;
#pragma unroll
        for (int j = 0; j < 32; j++) {
            __half2 hp = __floats2half2_rn(accf[2 * j], accf[2 * j + 1]);
            xshu[tid * 33 + j] = *(unsigned*)&hp;
        }
        __syncthreads();
        unsigned* Hh = (unsigned*)g_H;
        for (int i = tid; i < TB * 32; i += TB) {
            int node = i >> 5, c = i & 31;
            int vv = vbase + node;
            if (vv < Nn) Hh[(size_t)vv * 32 + c] = xshu[node * 33 + c];
        }
    } else if (IN == 64) {
        // stage through smem for coalesced store
#pragma unroll
        for (int c = 0; c < 64; c++) xsh[tid * 65 + c] = accf[c];
        __syncthreads();
        for (int i = tid; i < TB * 64; i += TB) {
            int node = i >> 6, c = i & 63;
            int vv = vbase + node;
            if (vv < Nn) g_H[(size_t)vv * 64 + c] = xsh[node * 65 + c];
        }
    } else {
        if (valid) {
            float4* o = (float4*)(g_H + (size_t)v * 64);
#pragma unroll
            for (int c = 0; c < 64; c += 4)
                o[c >> 2] = make_float4(accf[c], accf[c + 1], accf[c + 2], accf[c + 3]);
        }
    }
}

// ---------------- aggregation: warp/node, 2 edges per LDG.128 iteration ----------------
// lane = (p, q): p = lane>>4 edge parity, q = lane&15 owns channels 4q..4q+3.
// Weight computed in-register per lane (no precomputed weight pass).
template <int HEADS, bool ELU>
__global__ void __launch_bounds__(256) k_agg(const float* __restrict__ bias,
                      const float* __restrict__ gamma, const float* __restrict__ beta,
                      const float* __restrict__ mean,  const float* __restrict__ var,
                      int layer) {
    int lane = threadIdx.x & 31;
    int v = (blockIdx.x * blockDim.x + threadIdx.x) >> 5;
    if (v >= Nn) return;
    int start = g_rowoff[v], end = g_rowoff[v + 1];

    int p = lane >> 4;           // edge parity this lane handles
    int q = lane & 15;           // channel group (4 floats)
    int h = (HEADS == 4) ? (q >> 2) : 0;

    // per-lane head constants: alD_l and mv_l = lrelu(M_h + alD_h)
    float alD_l, mv_l;
    if (HEADS == 4) {
        float4 aD = ((const float4*)g_alD)[v];
        float M0 = decF(g_mEnc[layer * 4 + 0]);
        float M1 = decF(g_mEnc[layer * 4 + 1]);
        float M2 = decF(g_mEnc[layer * 4 + 2]);
        float M3 = decF(g_mEnc[layer * 4 + 3]);
        alD_l = (h & 2) ? ((h & 1) ? aD.w : aD.z) : ((h & 1) ? aD.y : aD.x);
        float M_l = (h & 2) ? ((h & 1) ? M3 : M2) : ((h & 1) ? M1 : M0);
        mv_l = lrelu(M_l + alD_l);
    } else {
        alD_l = g_alD[v];
        mv_l = lrelu(decF(g_mEnc[layer * 4]) + alD_l);
    }

    float4 acc = make_float4(0.f, 0.f, 0.f, 0.f);
    float wsum = 0.f;

    for (int base = start; base < end; base += 32) {
        int nn = end - base; if (nn > 32) nn = 32;
        int sl = g_adj[base + (lane < nn ? lane : nn - 1)];
        int npair = (nn + 1) >> 1;
#pragma unroll 4
        for (int j = 0; j < npair; j++) {
            int e = 2 * j + p;
            int s = __shfl_sync(0xffffffffu, sl, (e < nn) ? e : 0);
            float a = (HEADS == 4) ? g_alS[s * 4 + h] : g_alS[s];
            float w = __expf(lrelu(a + alD_l) - mv_l);
            if (e >= nn) w = 0.f;
            float4 hv = *(const float4*)(g_H + (size_t)s * 64 + q * 4);
            acc.x += w * hv.x;
            acc.y += w * hv.y;
            acc.z += w * hv.z;
            acc.w += w * hv.w;
            wsum += w;
        }
    }

    // combine edge parities: lanes (q) and (q+16) hold the two halves of the same channels
    acc.x += __shfl_xor_sync(0xffffffffu, acc.x, 16);
    acc.y += __shfl_xor_sync(0xffffffffu, acc.y, 16);
    acc.z += __shfl_xor_sync(0xffffffffu, acc.z, 16);
    acc.w += __shfl_xor_sync(0xffffffffu, acc.w, 16);
    // lanes with the same head accumulated identical w streams; xor16 gives the head total
    wsum += __shfl_xor_sync(0xffffffffu, wsum, 16);

    if (lane < 16) {
        int c = q * 4;
        float inv = 1.f / (wsum + 1e-16f);
        float4 b4 = *(const float4*)(bias + c);
        float4 mn = *(const float4*)(mean + c);
        float4 vr = *(const float4*)(var + c);
        float4 gm = *(const float4*)(gamma + c);
        float4 bt = *(const float4*)(beta + c);
        float4 r;
        r.x = (acc.x * inv + b4.x - mn.x) * rsqrtf(vr.x + BN_EPS) * gm.x + bt.x;
        r.y = (acc.y * inv + b4.y - mn.y) * rsqrtf(vr.y + BN_EPS) * gm.y + bt.y;
        r.z = (acc.z * inv + b4.z - mn.z) * rsqrtf(vr.z + BN_EPS) * gm.z + bt.z;
        r.w = (acc.w * inv + b4.w - mn.w) * rsqrtf(vr.w + BN_EPS) * gm.w + bt.w;
        if (ELU) {
            r.x = r.x > 0.f ? r.x : (expf(r.x) - 1.f);
            r.y = r.y > 0.f ? r.y : (expf(r.y) - 1.f);
            r.z = r.z > 0.f ? r.z : (expf(r.z) - 1.f);
            r.w = r.w > 0.f ? r.w : (expf(r.w) - 1.f);
        }
        *(float4*)(g_X + (size_t)v * 64 + c) = r;
    }
}

// ---------------- layer-3 aggregation fused with mean-pool (HEADS=1, fp16 g_H) ----
// Grid is exactly Nn/8 blocks x 8 warps, so every warp owns a valid node and
// __syncthreads() is safe. Gathers 128-B fp16 rows (half the traffic), fp32 math.
__global__ void __launch_bounds__(256) k_agg_pool(const float* __restrict__ bias,
                      const float* __restrict__ gamma, const float* __restrict__ beta,
                      const float* __restrict__ mean,  const float* __restrict__ var,
                      int layer) {
    __shared__ float psum[64];
    int tid = threadIdx.x;
    if (tid < 64) psum[tid] = 0.f;
    __syncthreads();

    int lane = tid & 31;
    int v = (blockIdx.x * blockDim.x + tid) >> 5;   // always < Nn (exact grid)
    int start = g_rowoff[v], end = g_rowoff[v + 1];

    int p = lane >> 4;
    int q = lane & 15;

    float alD_l = g_alD[v];
    float mv_l = lrelu(decF(g_mEnc[layer * 4]) + alD_l);

    float4 acc = make_float4(0.f, 0.f, 0.f, 0.f);
    float wsum = 0.f;
    const unsigned* Hh = (const unsigned*)g_H;   // fp16x2-packed rows (32 uints/row)

    for (int base = start; base < end; base += 32) {
        int nn = end - base; if (nn > 32) nn = 32;
        int sl = g_adj[base + (lane < nn ? lane : nn - 1)];
        int npair = (nn + 1) >> 1;
#pragma unroll 4
        for (int j = 0; j < npair; j++) {
            int e = 2 * j + p;
            int s = __shfl_sync(0xffffffffu, sl, (e < nn) ? e : 0);
            float a = g_alS[s];
            float w = __expf(lrelu(a + alD_l) - mv_l);
            if (e >= nn) w = 0.f;
            uint2 u = *(const uint2*)(Hh + (size_t)s * 32 + q * 2);
            float2 fa = __half22float2(*(const __half2*)&u.x);
            float2 fb = __half22float2(*(const __half2*)&u.y);
            acc.x += w * fa.x;
            acc.y += w * fa.y;
            acc.z += w * fb.x;
            acc.w += w * fb.y;
            wsum += w;
        }
    }

    acc.x += __shfl_xor_sync(0xffffffffu, acc.x, 16);
    acc.y += __shfl_xor_sync(0xffffffffu, acc.y, 16);
    acc.z += __shfl_xor_sync(0xffffffffu, acc.z, 16);
    acc.w += __shfl_xor_sync(0xffffffffu, acc.w, 16);
    wsum += __shfl_xor_sync(0xffffffffu, wsum, 16);

    if (lane < 16) {
        int c = q * 4;
        float inv = 1.f / (wsum + 1e-16f);
        float4 b4 = *(const float4*)(bias + c);
        float4 mn = *(const float4*)(mean + c);
        float4 vr = *(const float4*)(var + c);
        float4 gm = *(const float4*)(gamma + c);
        float4 bt = *(const float4*)(beta + c);
        float4 r;
        r.x = (acc.x * inv + b4.x - mn.x) * rsqrtf(vr.x + BN_EPS) * gm.x + bt.x;
        r.y = (acc.y * inv + b4.y - mn.y) * rsqrtf(vr.y + BN_EPS) * gm.y + bt.y;
        r.z = (acc.z * inv + b4.z - mn.z) * rsqrtf(vr.z + BN_EPS) * gm.z + bt.z;
        r.w = (acc.w * inv + b4.w - mn.w) * rsqrtf(vr.w + BN_EPS) * gm.w + bt.w;
        atomicAdd(&psum[c + 0], r.x);
        atomicAdd(&psum[c + 1], r.y);
        atomicAdd(&psum[c + 2], r.z);
        atomicAdd(&psum[c + 3], r.w);
    }
    __syncthreads();
    if (tid < 64) atomicAdd(&g_pooled2[tid * 32 + (blockIdx.x & 31)], psum[tid]);
}

// ---------------- heads ----------------
__global__ void __launch_bounds__(64) k_head(const float* __restrict__ cw1, const float* __restrict__ cb1,
                       const float* __restrict__ cw2, const float* __restrict__ cb2,
                       const float* __restrict__ rw1, const float* __restrict__ rb1,
                       const float* __restrict__ rw2, const float* __restrict__ rb2,
                       float* __restrict__ out) {
    __shared__ float pm[64], hc[32], hr[32];
    int t = threadIdx.x;    // 64 threads
    if (t < 64) {
        float s = 0.f;
#pragma unroll
        for (int j = 0; j < 32; j++) s += g_pooled2[t * 32 + j];
        pm[t] = s * (1.0f / (float)Nn);
    }
    __syncthreads();
    if (t < 32) {
        float sc = cb1[t], sr = rb1[t];
        for (int k = 0; k < 64; k++) {
            sc += cw1[t * 64 + k] * pm[k];
            sr += rw1[t * 64 + k] * pm[k];
        }
        hc[t] = fmaxf(sc, 0.f);
        hr[t] = fmaxf(sr, 0.f);
    }
    __syncthreads();
    if (t < 3) {
        float s = cb2[t];
        for (int k = 0; k < 32; k++) s += cw2[t * 32 + k] * hc[k];
        out[t] = s;
    }
    if (t == 3) {
        float s = rb2[0];
        for (int k = 0; k < 32; k++) s += rw2[k] * hr[k];
        out[3] = s;
    }
}

// ---------------- launch ----------------
extern "C" void kernel_launch(void* const* d_in, const int* in_sizes, int n_in,
                              void* d_out, int out_size) {
    const float* x   = (const float*)d_in[0];
    const int*   ei  = (const int*)d_in[1];
    int E = in_sizes[1] / 2;
    if (E > Emax) E = Emax;
    const int* srcA = ei;
    const int* dstA = ei + E;
    const float* W1  = (const float*)d_in[2];
    const float* a1s = (const float*)d_in[3];
    const float* a1d = (const float*)d_in[4];
    const float* b1  = (const float*)d_in[5];
    const float* W2  = (const float*)d_in[6];
    const float* a2s = (const float*)d_in[7];
    const float* a2d = (const float*)d_in[8];
    const float* b2  = (const float*)d_in[9];
    const float* W3  = (const float*)d_in[10];
    const float* a3s = (const float*)d_in[11];
    const float* a3d = (const float*)d_in[12];
    const float* b3  = (const float*)d_in[13];
    const float* bg  = (const float*)d_in[14];
    const float* bb  = (const float*)d_in[15];
    const float* bm  = (const float*)d_in[16];
    const float* bv  = (const float*)d_in[17];
    const float* cw1 = (const float*)d_in[18];
    const float* cb1 = (const float*)d_in[19];
    const float* cw2 = (const float*)d_in[20];
    const float* cb2 = (const float*)d_in[21];
    const float* rw1 = (const float*)d_in[22];
    const float* rb1 = (const float*)d_in[23];
    const float* rw2 = (const float*)d_in[24];
    const float* rb2 = (const float*)d_in[25];
    float* out = (float*)d_out;

    int ET = E + Nn;

    // CSR build (every call; deterministic work)
    k_init<<<(Nn + 255) / 256, 256>>>();
    k_count<<<(E + 255) / 256, 256>>>(dstA, E);
    k_scan1<<<NB, 1024>>>();
    k_scan2<<<1, 128>>>(ET);
    k_scan3<<<NB, 1024>>>();
    k_fill<<<(ET + 255) / 256, 256>>>(srcA, dstA, E);

    int linGrid = (Nn + 127) / 128;
    int aggGrid = (Nn + 7) / 8;   // exact: 12500 * 8 warps = 100000 nodes

    // layer 1
    k_lin<5, 4, false><<<linGrid, 128>>>(x, W1, a1s, a1d, 0);
    k_agg<4, true><<<aggGrid, 256>>>(b1, bg + 0,  bb + 0,  bm + 0,  bv + 0,  0);
    // layer 2
    k_lin<64, 4, false><<<linGrid, 128>>>(nullptr, W2, a2s, a2d, 1);
    k_agg<4, true><<<aggGrid, 256>>>(b2, bg + 64, bb + 64, bm + 64, bv + 64, 1);
    // layer 3 (fp16 feature rows; aggregation fused with mean-pool)
    k_lin<64, 1, true><<<linGrid, 128>>>(nullptr, W3, a3s, a3d, 2);
    k_agg_pool<<<aggGrid, 256>>>(b3, bg + 128, bb + 128, bm + 128, bv + 128, 2);

    // heads
    k_head<<<1, 64>>>(cw1, cb1, cw2, cb2, rw1, rb1, rw2, rb2, out);
}

// round 13
// speedup vs baseline: 1.0735x; 1.0735x over previous
#include <cuda_runtime.h>
#include <cuda_fp16.h>
#include <math.h>

#define Nn 100000
#define Emax 1600000
#define ETmax (Emax + Nn)
#define NB 98                 // (Nn + 1023) / 1024
#define BN_EPS 1e-5f
#define LRELU 0.2f

// ---- scratch (static device globals; no allocation) ----
__device__ float g_H[Nn * 64];        // transformed features: fp16x2-packed rows (32 u32/row)
__device__ float g_X[Nn * 64];        // post-layer features (fp32)
__device__ float g_alS[Nn * 4];
__device__ float g_alD[Nn * 4];
__device__ int   g_deg[Nn];
__device__ int   g_rowoff[Nn + 1];
__device__ int   g_cursor[Nn];
__device__ int   g_adj[ETmax];
__device__ int   g_bsum[NB];
__device__ int   g_boff[NB];
__device__ float g_pooled2[64 * 32];  // [channel][slot] partial pooled sums
__device__ unsigned g_mEnc[12];       // order-encoded per-layer per-head global alS max

// order-preserving float<->uint encoding (for atomicMax on floats incl. negatives)
__device__ __forceinline__ unsigned encF(float f) {
    unsigned u = __float_as_uint(f);
    return (u & 0x80000000u) ? ~u : (u | 0x80000000u);
}
__device__ __forceinline__ float decF(unsigned e) {
    unsigned u = (e & 0x80000000u) ? (e & 0x7FFFFFFFu) : ~e;
    return __uint_as_float(u);
}
__device__ __forceinline__ float lrelu(float x) { return x > 0.f ? x : LRELU * x; }

// ---------------- CSR build ----------------
__global__ void __launch_bounds__(256) k_init() {
    int i = blockIdx.x * blockDim.x + threadIdx.x;
    if (i < Nn) g_deg[i] = 1;          // self-loop
    if (i < 64 * 32) g_pooled2[i] = 0.f;
    if (i < 12) g_mEnc[i] = 0u;        // below any real encoded float
}

__global__ void __launch_bounds__(256) k_count(const int* __restrict__ dst, int E) {
    int i = blockIdx.x * blockDim.x + threadIdx.x;
    if (i < E) atomicAdd(&g_deg[dst[i]], 1);
}

// phase 1: per-1024-block sums
__global__ void __launch_bounds__(1024) k_scan1() {
    int i = blockIdx.x * 1024 + threadIdx.x;
    int lane = threadIdx.x & 31, wid = threadIdx.x >> 5;
    int d = (i < Nn) ? g_deg[i] : 0;
#pragma unroll
    for (int off = 16; off; off >>= 1) d += __shfl_xor_sync(0xffffffffu, d, off);
    __shared__ int ws[32];
    if (lane == 0) ws[wid] = d;
    __syncthreads();
    if (threadIdx.x < 32) {
        int t = ws[threadIdx.x];
#pragma unroll
        for (int off = 16; off; off >>= 1) t += __shfl_xor_sync(0xffffffffu, t, off);
        if (threadIdx.x == 0) g_bsum[blockIdx.x] = t;
    }
}

// phase 2: scan 98 block sums (1 block, 128 threads)
__global__ void __launch_bounds__(128) k_scan2(int total) {
    int t = threadIdx.x;
    int lane = t & 31, wid = t >> 5;
    int v = (t < NB) ? g_bsum[t] : 0;
    int x = v;
#pragma unroll
    for (int off = 1; off < 32; off <<= 1) {
        int y = __shfl_up_sync(0xffffffffu, x, off);
        if (lane >= off) x += y;
    }
    __shared__ int ws[4];
    if (lane == 31) ws[wid] = x;
    __syncthreads();
    int add = 0;
#pragma unroll
    for (int w = 0; w < 4; w++) if (w < wid) add += ws[w];
    if (t < NB) g_boff[t] = x + add - v;   // exclusive
    if (t == 0) g_rowoff[Nn] = total;
}

// phase 3: per-block exclusive scan + scatter rowoff/cursor
__global__ void __launch_bounds__(1024) k_scan3() {
    int i = blockIdx.x * 1024 + threadIdx.x;
    int lane = threadIdx.x & 31, wid = threadIdx.x >> 5;
    int d = (i < Nn) ? g_deg[i] : 0;
    int x = d;
#pragma unroll
    for (int off = 1; off < 32; off <<= 1) {
        int y = __shfl_up_sync(0xffffffffu, x, off);
        if (lane >= off) x += y;
    }
    __shared__ int ws[32];
    if (lane == 31) ws[wid] = x;
    __syncthreads();
    if (wid == 0) {
        int y = ws[lane];
        int z = y;
#pragma unroll
        for (int off = 1; off < 32; off <<= 1) {
            int q = __shfl_up_sync(0xffffffffu, z, off);
            if (lane >= off) z += q;
        }
        ws[lane] = z - y;   // exclusive warp offsets
    }
    __syncthreads();
    int excl = x - d + ws[wid] + g_boff[blockIdx.x];
    if (i < Nn) { g_rowoff[i] = excl; g_cursor[i] = excl; }
}

__global__ void __launch_bounds__(256) k_fill(const int* __restrict__ src,
                                              const int* __restrict__ dst, int E) {
    int i = blockIdx.x * blockDim.x + threadIdx.x;
    int tot = E + Nn;
    if (i >= tot) return;
    int s, d;
    if (i < E) { s = src[i]; d = dst[i]; }
    else       { s = i - E; d = s; }
    int p = atomicAdd(&g_cursor[d], 1);
    g_adj[p] = s;
}

// ---------------- linear + attention-logit kernel (f32x2 packed FMA) ----------------
// g_H rows are stored as 64 fp16 (128 B, fp16x2-packed). alS/alD stay fp32.
template <int IN, int HEADS>
__global__ void __launch_bounds__(128) k_lin(const float* __restrict__ xin,
                                             const float* __restrict__ W,
                                             const float* __restrict__ asrc,
                                             const float* __restrict__ adst,
                                             int layer) {
    constexpr int TB = 128;
    constexpr int XS = (IN == 64) ? 65 : IN;
    __shared__ __align__(16) float Wsh[64 * IN];
    __shared__ __align__(16) float xsh[TB * ((IN == 64) ? 65 : IN)];
    int tid = threadIdx.x;
    int lane = tid & 31;
    int vbase = blockIdx.x * TB;

    for (int i = tid; i < 64 * IN; i += TB) {
        int c = i / IN, k = i % IN;
        Wsh[k * 64 + c] = W[i];          // transposed: Wsh[k][c]
    }
    const float* srcp = (IN == 64) ? (const float*)g_X : xin;
    for (int i = tid; i < TB * IN; i += TB) {
        int node = i / IN, k = i % IN;
        int v = vbase + node;
        xsh[node * XS + k] = (v < Nn) ? srcp[(size_t)v * IN + k] : 0.f;
    }
    __syncthreads();

    unsigned long long acc2[32];
#pragma unroll
    for (int j = 0; j < 32; j++) acc2[j] = 0ull;   // bits 0 == {+0.f,+0.f}

#pragma unroll 4
    for (int k = 0; k < IN; k++) {
        float xk = xsh[tid * XS + k];
        unsigned long long xk2;
        asm("mov.b64 %0, {%1, %1};" : "=l"(xk2) : "f"(xk));
        const unsigned long long* Wp = (const unsigned long long*)(Wsh + k * 64);
#pragma unroll
        for (int j = 0; j < 32; j++) {
            asm("fma.rn.f32x2 %0, %1, %2, %0;" : "+l"(acc2[j]) : "l"(Wp[j]), "l"(xk2));
        }
    }

    float accf[64];
#pragma unroll
    for (int j = 0; j < 32; j++) {
        asm("mov.b64 {%0, %1}, %2;" : "=f"(accf[2 * j]), "=f"(accf[2 * j + 1]) : "l"(acc2[j]));
    }

    int v = vbase + tid;
    bool valid = (v < Nn);
    constexpr int C = 64 / HEADS;
    float mx[HEADS];
#pragma unroll
    for (int h = 0; h < HEADS; h++) {
        float s1 = 0.f, s2 = 0.f;
#pragma unroll
        for (int j = 0; j < C; j++) {
            float t = accf[h * C + j];
            s1 += t * asrc[h * C + j];
            s2 += t * adst[h * C + j];
        }
        if (valid) {
            g_alS[(size_t)v * HEADS + h] = s1;
            g_alD[(size_t)v * HEADS + h] = s2;
        }
        mx[h] = valid ? s1 : -3.4e38f;
    }
    // warp-reduce max per head, one atomic per warp per head
#pragma unroll
    for (int h = 0; h < HEADS; h++) {
#pragma unroll
        for (int off = 16; off; off >>= 1)
            mx[h] = fmaxf(mx[h], __shfl_xor_sync(0xffffffffu, mx[h], off));
        if (lane == 0) atomicMax(&g_mEnc[layer * 4 + h], encF(mx[h]));
    }

    // ---- store row as fp16x2-packed (32 u32) ----
    unsigned hw[32];
#pragma unroll
    for (int j = 0; j < 32; j++) {
        __half2 hp = __floats2half2_rn(accf[2 * j], accf[2 * j + 1]);
        hw[j] = *(unsigned*)&hp;
    }
    unsigned* Hh = (unsigned*)g_H;
    if (IN == 64) {
        // stage through smem for coalesced store (xsh is large enough: TB*33 u32)
        __syncthreads();
        unsigned* xshu = (unsigned*)xsh;
#pragma unroll
        for (int j = 0; j < 32; j++) xshu[tid * 33 + j] = hw[j];
        __syncthreads();
        for (int i = tid; i < TB * 32; i += TB) {
            int node = i >> 5, c = i & 31;
            int vv = vbase + node;
            if (vv < Nn) Hh[(size_t)vv * 32 + c] = xshu[node * 33 + c];
        }
    } else {
        // xsh too small to stage; direct uint4 row stores (4 x STG.128 per thread)
        if (valid) {
            uint4* o = (uint4*)(Hh + (size_t)v * 32);
#pragma unroll
            for (int j = 0; j < 8; j++)
                o[j] = make_uint4(hw[4 * j], hw[4 * j + 1], hw[4 * j + 2], hw[4 * j + 3]);
        }
    }
}

// ---------------- aggregation: warp/node, 2 edges per LDG.64 iteration ----------------
// lane = (p, q): p = lane>>4 edge parity, q = lane&15 owns channels 4q..4q+3.
// g_H rows are fp16x2-packed (128 B); weights/accumulation in fp32.
template <int HEADS, bool ELU>
__global__ void __launch_bounds__(256) k_agg(const float* __restrict__ bias,
                      const float* __restrict__ gamma, const float* __restrict__ beta,
                      const float* __restrict__ mean,  const float* __restrict__ var,
                      int layer) {
    int lane = threadIdx.x & 31;
    int v = (blockIdx.x * blockDim.x + threadIdx.x) >> 5;
    if (v >= Nn) return;
    int start = g_rowoff[v], end = g_rowoff[v + 1];

    int p = lane >> 4;           // edge parity this lane handles
    int q = lane & 15;           // channel group (4 floats)
    int h = (HEADS == 4) ? (q >> 2) : 0;

    // per-lane head constants: alD_l and mv_l = lrelu(M_h + alD_h)
    float alD_l, mv_l;
    if (HEADS == 4) {
        float4 aD = ((const float4*)g_alD)[v];
        float M0 = decF(g_mEnc[layer * 4 + 0]);
        float M1 = decF(g_mEnc[layer * 4 + 1]);
        float M2 = decF(g_mEnc[layer * 4 + 2]);
        float M3 = decF(g_mEnc[layer * 4 + 3]);
        alD_l = (h & 2) ? ((h & 1) ? aD.w : aD.z) : ((h & 1) ? aD.y : aD.x);
        float M_l = (h & 2) ? ((h & 1) ? M3 : M2) : ((h & 1) ? M1 : M0);
        mv_l = lrelu(M_l + alD_l);
    } else {
        alD_l = g_alD[v];
        mv_l = lrelu(decF(g_mEnc[layer * 4]) + alD_l);
    }

    float4 acc = make_float4(0.f, 0.f, 0.f, 0.f);
    float wsum = 0.f;
    const unsigned* Hh = (const unsigned*)g_H;

    for (int base = start; base < end; base += 32) {
        int nn = end - base; if (nn > 32) nn = 32;
        int sl = g_adj[base + (lane < nn ? lane : nn - 1)];
        int npair = (nn + 1) >> 1;
#pragma unroll 4
        for (int j = 0; j < npair; j++) {
            int e = 2 * j + p;
            int s = __shfl_sync(0xffffffffu, sl, (e < nn) ? e : 0);
            float a = (HEADS == 4) ? g_alS[s * 4 + h] : g_alS[s];
            float w = __expf(lrelu(a + alD_l) - mv_l);
            if (e >= nn) w = 0.f;
            uint2 u = *(const uint2*)(Hh + (size_t)s * 32 + q * 2);
            float2 fa = __half22float2(*(const __half2*)&u.x);
            float2 fb = __half22float2(*(const __half2*)&u.y);
            acc.x += w * fa.x;
            acc.y += w * fa.y;
            acc.z += w * fb.x;
            acc.w += w * fb.y;
            wsum += w;
        }
    }

    // combine edge parities: lanes (q) and (q+16) hold the two halves of the same channels
    acc.x += __shfl_xor_sync(0xffffffffu, acc.x, 16);
    acc.y += __shfl_xor_sync(0xffffffffu, acc.y, 16);
    acc.z += __shfl_xor_sync(0xffffffffu, acc.z, 16);
    acc.w += __shfl_xor_sync(0xffffffffu, acc.w, 16);
    // lanes with the same head accumulated identical w streams; xor16 gives the head total
    wsum += __shfl_xor_sync(0xffffffffu, wsum, 16);

    if (lane < 16) {
        int c = q * 4;
        float inv = 1.f / (wsum + 1e-16f);
        float4 b4 = *(const float4*)(bias + c);
        float4 mn = *(const float4*)(mean + c);
        float4 vr = *(const float4*)(var + c);
        float4 gm = *(const float4*)(gamma + c);
        float4 bt = *(const float4*)(beta + c);
        float4 r;
        r.x = (acc.x * inv + b4.x - mn.x) * rsqrtf(vr.x + BN_EPS) * gm.x + bt.x;
        r.y = (acc.y * inv + b4.y - mn.y) * rsqrtf(vr.y + BN_EPS) * gm.y + bt.y;
        r.z = (acc.z * inv + b4.z - mn.z) * rsqrtf(vr.z + BN_EPS) * gm.z + bt.z;
        r.w = (acc.w * inv + b4.w - mn.w) * rsqrtf(vr.w + BN_EPS) * gm.w + bt.w;
        if (ELU) {
            r.x = r.x > 0.f ? r.x : (expf(r.x) - 1.f);
            r.y = r.y > 0.f ? r.y : (expf(r.y) - 1.f);
            r.z = r.z > 0.f ? r.z : (expf(r.z) - 1.f);
            r.w = r.w > 0.f ? r.w : (expf(r.w) - 1.f);
        }
        *(float4*)(g_X + (size_t)v * 64 + c) = r;
    }
}

// ---------------- layer-3 aggregation fused with mean-pool (HEADS=1, fp16 g_H) ----
// Grid is exactly Nn/8 blocks x 8 warps, so every warp owns a valid node and
// __syncthreads() is safe. Gathers 128-B fp16 rows, fp32 math, no g_X store.
__global__ void __launch_bounds__(256) k_agg_pool(const float* __restrict__ bias,
                      const float* __restrict__ gamma, const float* __restrict__ beta,
                      const float* __restrict__ mean,  const float* __restrict__ var,
                      int layer) {
    __shared__ float psum[64];
    int tid = threadIdx.x;
    if (tid < 64) psum[tid] = 0.f;
    __syncthreads();

    int lane = tid & 31;
    int v = (blockIdx.x * blockDim.x + tid) >> 5;   // always < Nn (exact grid)
    int start = g_rowoff[v], end = g_rowoff[v + 1];

    int p = lane >> 4;
    int q = lane & 15;

    float alD_l = g_alD[v];
    float mv_l = lrelu(decF(g_mEnc[layer * 4]) + alD_l);

    float4 acc = make_float4(0.f, 0.f, 0.f, 0.f);
    float wsum = 0.f;
    const unsigned* Hh = (const unsigned*)g_H;

    for (int base = start; base < end; base += 32) {
        int nn = end - base; if (nn > 32) nn = 32;
        int sl = g_adj[base + (lane < nn ? lane : nn - 1)];
        int npair = (nn + 1) >> 1;
#pragma unroll 4
        for (int j = 0; j < npair; j++) {
            int e = 2 * j + p;
            int s = __shfl_sync(0xffffffffu, sl, (e < nn) ? e : 0);
            float a = g_alS[s];
            float w = __expf(lrelu(a + alD_l) - mv_l);
            if (e >= nn) w = 0.f;
            uint2 u = *(const uint2*)(Hh + (size_t)s * 32 + q * 2);
            float2 fa = __half22float2(*(const __half2*)&u.x);
            float2 fb = __half22float2(*(const __half2*)&u.y);
            acc.x += w * fa.x;
            acc.y += w * fa.y;
            acc.z += w * fb.x;
            acc.w += w * fb.y;
            wsum += w;
        }
    }

    acc.x += __shfl_xor_sync(0xffffffffu, acc.x, 16);
    acc.y += __shfl_xor_sync(0xffffffffu, acc.y, 16);
    acc.z += __shfl_xor_sync(0xffffffffu, acc.z, 16);
    acc.w += __shfl_xor_sync(0xffffffffu, acc.w, 16);
    wsum += __shfl_xor_sync(0xffffffffu, wsum, 16);

    if (lane < 16) {
        int c = q * 4;
        float inv = 1.f / (wsum + 1e-16f);
        float4 b4 = *(const float4*)(bias + c);
        float4 mn = *(const float4*)(mean + c);
        float4 vr = *(const float4*)(var + c);
        float4 gm = *(const float4*)(gamma + c);
        float4 bt = *(const float4*)(beta + c);
        float4 r;
        r.x = (acc.x * inv + b4.x - mn.x) * rsqrtf(vr.x + BN_EPS) * gm.x + bt.x;
        r.y = (acc.y * inv + b4.y - mn.y) * rsqrtf(vr.y + BN_EPS) * gm.y + bt.y;
        r.z = (acc.z * inv + b4.z - mn.z) * rsqrtf(vr.z + BN_EPS) * gm.z + bt.z;
        r.w = (acc.w * inv + b4.w - mn.w) * rsqrtf(vr.w + BN_EPS) * gm.w + bt.w;
        atomicAdd(&psum[c + 0], r.x);
        atomicAdd(&psum[c + 1], r.y);
        atomicAdd(&psum[c + 2], r.z);
        atomicAdd(&psum[c + 3], r.w);
    }
    __syncthreads();
    if (tid < 64) atomicAdd(&g_pooled2[tid * 32 + (blockIdx.x & 31)], psum[tid]);
}

// ---------------- heads ----------------
__global__ void __launch_bounds__(64) k_head(const float* __restrict__ cw1, const float* __restrict__ cb1,
                       const float* __restrict__ cw2, const float* __restrict__ cb2,
                       const float* __restrict__ rw1, const float* __restrict__ rb1,
                       const float* __restrict__ rw2, const float* __restrict__ rb2,
                       float* __restrict__ out) {
    __shared__ float pm[64], hc[32], hr[32];
    int t = threadIdx.x;    // 64 threads
    if (t < 64) {
        float s = 0.f;
#pragma unroll
        for (int j = 0; j < 32; j++) s += g_pooled2[t * 32 + j];
        pm[t] = s * (1.0f / (float)Nn);
    }
    __syncthreads();
    if (t < 32) {
        float sc = cb1[t], sr = rb1[t];
        for (int k = 0; k < 64; k++) {
            sc += cw1[t * 64 + k] * pm[k];
            sr += rw1[t * 64 + k] * pm[k];
        }
        hc[t] = fmaxf(sc, 0.f);
        hr[t] = fmaxf(sr, 0.f);
    }
    __syncthreads();
    if (t < 3) {
        float s = cb2[t];
        for (int k = 0; k < 32; k++) s += cw2[t * 32 + k] * hc[k];
        out[t] = s;
    }
    if (t == 3) {
        float s = rb2[0];
        for (int k = 0; k < 32; k++) s += rw2[k] * hr[k];
        out[3] = s;
    }
}

// ---------------- launch ----------------
extern "C" void kernel_launch(void* const* d_in, const int* in_sizes, int n_in,
                              void* d_out, int out_size) {
    const float* x   = (const float*)d_in[0];
    const int*   ei  = (const int*)d_in[1];
    int E = in_sizes[1] / 2;
    if (E > Emax) E = Emax;
    const int* srcA = ei;
    const int* dstA = ei + E;
    const float* W1  = (const float*)d_in[2];
    const float* a1s = (const float*)d_in[3];
    const float* a1d = (const float*)d_in[4];
    const float* b1  = (const float*)d_in[5];
    const float* W2  = (const float*)d_in[6];
    const float* a2s = (const float*)d_in[7];
    const float* a2d = (const float*)d_in[8];
    const float* b2  = (const float*)d_in[9];
    const float* W3  = (const float*)d_in[10];
    const float* a3s = (const float*)d_in[11];
    const float* a3d = (const float*)d_in[12];
    const float* b3  = (const float*)d_in[13];
    const float* bg  = (const float*)d_in[14];
    const float* bb  = (const float*)d_in[15];
    const float* bm  = (const float*)d_in[16];
    const float* bv  = (const float*)d_in[17];
    const float* cw1 = (const float*)d_in[18];
    const float* cb1 = (const float*)d_in[19];
    const float* cw2 = (const float*)d_in[20];
    const float* cb2 = (const float*)d_in[21];
    const float* rw1 = (const float*)d_in[22];
    const float* rb1 = (const float*)d_in[23];
    const float* rw2 = (const float*)d_in[24];
    const float* rb2 = (const float*)d_in[25];
    float* out = (float*)d_out;

    int ET = E + Nn;

    // CSR build (every call; deterministic work)
    k_init<<<(Nn + 255) / 256, 256>>>();
    k_count<<<(E + 255) / 256, 256>>>(dstA, E);
    k_scan1<<<NB, 1024>>>();
    k_scan2<<<1, 128>>>(ET);
    k_scan3<<<NB, 1024>>>();
    k_fill<<<(ET + 255) / 256, 256>>>(srcA, dstA, E);

    int linGrid = (Nn + 127) / 128;
    int aggGrid = (Nn + 7) / 8;   // exact: 12500 * 8 warps = 100000 nodes

    // layer 1
    k_lin<5, 4><<<linGrid, 128>>>(x, W1, a1s, a1d, 0);
    k_agg<4, true><<<aggGrid, 256>>>(b1, bg + 0,  bb + 0,  bm + 0,  bv + 0,  0);
    // layer 2
    k_lin<64, 4><<<linGrid, 128>>>(nullptr, W2, a2s, a2d, 1);
    k_agg<4, true><<<aggGrid, 256>>>(b2, bg + 64, bb + 64, bm + 64, bv + 64, 1);
    // layer 3 (aggregation fused with mean-pool; no g_X store)
    k_lin<64, 1><<<linGrid, 128>>>(nullptr, W3, a3s, a3d, 2);
    k_agg_pool<<<aggGrid, 256>>>(b3, bg + 128, bb + 128, bm + 128, bv + 128, 2);

    // heads
    k_head<<<1, 64>>>(cw1, cb1, cw2, cb2, rw1, rb1, rw2, rb2, out);
}